// round 16
// baseline (speedup 1.0000x reference)
#include <cuda_runtime.h>
#include <cuda_bf16.h>
#include <math.h>
#include <stdint.h>

#define NN 50000
#define EE 800000
#define GG 512
#define LN_EPS 1e-5f
#define NEG_SLOPE 0.2f
#define NCHUNKS ((NN + 1023) / 1024)

// ---------------- device scratch ----------------
__device__ float g_xl[NN * 256];
__device__ float g_xr[NN * 256];
__device__ float g_h[NN * 256];
__device__ float g_acc[NN * 256];
__device__ int   g_rowptr[NN + 1];
__device__ int   g_cnt[NN];
__device__ int   g_eidx[EE];            // holds SRC node id per CSR slot
__device__ int   g_part[64];
__device__ float g_red[6];              // (sum, sumsq) per layer
__device__ float g_pool[GG * 64];
__device__ float g_pcnt[GG];

// side stream + fork/join events
static cudaStream_t g_s1;
static cudaEvent_t  g_ev0, g_ev1;
namespace {
struct StreamInit {
    StreamInit() {
        cudaStreamCreateWithFlags(&g_s1, cudaStreamNonBlocking);
        cudaEventCreateWithFlags(&g_ev0, cudaEventDisableTiming);
        cudaEventCreateWithFlags(&g_ev1, cudaEventDisableTiming);
    }
};
StreamInit s_streamInit;
}

__device__ __forceinline__ float lrelu(float v) {
    return v > 0.f ? v : NEG_SLOPE * v;
}

__device__ __forceinline__ uint32_t smem_u32(const void* p) {
    uint32_t a;
    asm("{ .reg .u64 t; cvta.to.shared.u64 t, %1; cvt.u32.u64 %0, t; }" : "=r"(a) : "l"(p));
    return a;
}

__device__ __forceinline__ void cp16(uint32_t dst, const void* src, int srcsize) {
    asm volatile("cp.async.cg.shared.global [%0], [%1], 16, %2;"
                 :: "r"(dst), "l"(src), "r"(srcsize) : "memory");
}
#define CP_COMMIT() asm volatile("cp.async.commit_group;" ::: "memory")
#define CP_WAIT1()  asm volatile("cp.async.wait_group 1;" ::: "memory")
#define CP_WAIT0()  asm volatile("cp.async.wait_group 0;" ::: "memory")

// ---------------- init / CSR build ----------------
__global__ void k_zero_misc() {
    int i = blockIdx.x * blockDim.x + threadIdx.x;
    if (i < NN) g_cnt[i] = 0;
    if (i < GG * 64) g_pool[i] = 0.f;
    if (i < GG) g_pcnt[i] = 0.f;
    if (i < 6) g_red[i] = 0.f;
}

__global__ void k_hist_pcnt(const int* __restrict__ dst, const int* __restrict__ batch) {
    int e = blockIdx.x * blockDim.x + threadIdx.x;
    if (e < EE) atomicAdd(&g_cnt[dst[e]], 1);
    if (e < NN) atomicAdd(&g_pcnt[batch[e]], 1.f);
}

__global__ __launch_bounds__(1024) void k_scan1() {
    __shared__ int sh[1024];
    int b = blockIdx.x;
    int tid = threadIdx.x;
    int i = b * 1024 + tid;
    int v = (i < NN) ? g_cnt[i] : 0;
    sh[tid] = v;
    __syncthreads();
    #pragma unroll
    for (int off = 1; off < 1024; off <<= 1) {
        int t = (tid >= off) ? sh[tid - off] : 0;
        __syncthreads();
        sh[tid] += t;
        __syncthreads();
    }
    if (i < NN) g_rowptr[i + 1] = sh[tid];
    if (tid == 1023) g_part[b] = sh[1023];
}

__global__ __launch_bounds__(64) void k_scan2() {
    __shared__ int sh[64];
    int tid = threadIdx.x;
    int v = (tid < NCHUNKS) ? g_part[tid] : 0;
    sh[tid] = v;
    __syncthreads();
    #pragma unroll
    for (int off = 1; off < 64; off <<= 1) {
        int t = (tid >= off) ? sh[tid - off] : 0;
        __syncthreads();
        sh[tid] += t;
        __syncthreads();
    }
    g_part[tid] = sh[tid] - v;
}

__global__ void k_scan3() {
    int i = blockIdx.x * blockDim.x + threadIdx.x;
    if (i == 0) g_rowptr[0] = 0;
    if (i < NN) {
        int incl = g_rowptr[i + 1] + g_part[i >> 10];
        g_rowptr[i + 1] = incl;
        g_cnt[i] = incl - g_cnt[i];
    }
}

__global__ void k_scatter(const int* __restrict__ src, const int* __restrict__ dst) {
    int e = blockIdx.x * blockDim.x + threadIdx.x;
    if (e < EE) {
        int pos = atomicAdd(&g_cnt[dst[e]], 1);
        g_eidx[pos] = src[e];
    }
}

// ---------------- fused dual GEMM (BN=128): at FFMA roof -------------------
template <int K, int M>
__global__ __launch_bounds__(256, 2) void k_gemm_dual(
    const float* __restrict__ X,
    const float* __restrict__ Wl, const float* __restrict__ bl,
    const float* __restrict__ Wr, const float* __restrict__ br,
    float* __restrict__ Yl, float* __restrict__ Yr, int rows)
{
    constexpr int NC = K / 16;
    __shared__ float As[3][128][20];
    __shared__ float Bs[3][16][132];

    int block_row = blockIdx.y * 128;
    int block_col = blockIdx.x * 128;
    int t = threadIdx.x;
    int tx = t & 15;
    int ty = t >> 4;

    uint32_t sA = smem_u32(&As[0][0][0]);
    uint32_t sB = smem_u32(&Bs[0][0][0]);
    constexpr uint32_t A_BUF = 128 * 20 * 4;
    constexpr uint32_t B_BUF = 16 * 132 * 4;

    int a_r[2], a_q[2];
    #pragma unroll
    for (int it = 0; it < 2; it++) {
        int slot = t + it * 256;
        a_r[it] = slot >> 2;
        a_q[it] = slot & 3;
    }
    int b_k[2], b_n[2];
    const float* Wp[2];
    #pragma unroll
    for (int it = 0; it < 2; it++) {
        int slot = t + it * 256;
        b_k[it] = slot >> 5;
        b_n[it] = (slot & 31) * 4;
        int gc = block_col + b_n[it];
        Wp[it] = (gc < M) ? (Wl + gc) : (Wr + gc - M);
    }

    float acc[8][8];
    #pragma unroll
    for (int i = 0; i < 8; i++)
        #pragma unroll
        for (int j = 0; j < 8; j++) acc[i][j] = 0.f;

    auto issue_copy = [&](int c, int buf) {
        int k0 = c * 16;
        #pragma unroll
        for (int it = 0; it < 2; it++) {
            int grow = block_row + a_r[it];
            uint32_t dst = sA + buf * A_BUF + (a_r[it] * 20 + a_q[it] * 4) * 4;
            cp16(dst, X + (size_t)grow * K + k0 + a_q[it] * 4, (grow < rows) ? 16 : 0);
        }
        #pragma unroll
        for (int it = 0; it < 2; it++) {
            uint32_t dst = sB + buf * B_BUF + (b_k[it] * 132 + b_n[it]) * 4;
            cp16(dst, Wp[it] + (size_t)(k0 + b_k[it]) * M, 16);
        }
        CP_COMMIT();
    };

    issue_copy(0, 0);
    if (NC > 1) issue_copy(1, 1);

    #pragma unroll 1
    for (int c = 0; c < NC; c++) {
        int cb = c % 3;
        if (c + 1 < NC) { CP_WAIT1(); } else { CP_WAIT0(); }
        __syncthreads();
        if (c + 2 < NC) issue_copy(c + 2, (c + 2) % 3);

        const float* pA = &As[cb][ty * 8][0];
        const float* pB = &Bs[cb][0][tx * 8];

        float fa[2][8], fb[2][8];
        #pragma unroll
        for (int i = 0; i < 8; i++) fa[0][i] = pA[i * 20];
        *reinterpret_cast<float4*>(&fb[0][0]) = *reinterpret_cast<const float4*>(pB);
        *reinterpret_cast<float4*>(&fb[0][4]) = *reinterpret_cast<const float4*>(pB + 4);

        #pragma unroll
        for (int k = 0; k < 16; k++) {
            int cur = k & 1, nxt = (k + 1) & 1;
            if (k < 15) {
                #pragma unroll
                for (int i = 0; i < 8; i++) fa[nxt][i] = pA[i * 20 + k + 1];
                const float* pBn = pB + (k + 1) * 132;
                *reinterpret_cast<float4*>(&fb[nxt][0]) = *reinterpret_cast<const float4*>(pBn);
                *reinterpret_cast<float4*>(&fb[nxt][4]) = *reinterpret_cast<const float4*>(pBn + 4);
            }
            #pragma unroll
            for (int i = 0; i < 8; i++)
                #pragma unroll
                for (int j = 0; j < 8; j++)
                    acc[i][j] += fa[cur][i] * fb[cur][j];
        }
    }

    int gce = block_col + tx * 8;
    float* Y = (gce < M) ? Yl : Yr;
    const float* bb = (gce < M) ? bl : br;
    int col = (gce < M) ? gce : gce - M;
    float bv[8];
    #pragma unroll
    for (int j = 0; j < 8; j++) bv[j] = bb[col + j];

    #pragma unroll
    for (int i = 0; i < 8; i++) {
        int r = block_row + ty * 8 + i;
        if (r < rows) {
            float4 o0, o1;
            o0.x = acc[i][0] + bv[0]; o0.y = acc[i][1] + bv[1];
            o0.z = acc[i][2] + bv[2]; o0.w = acc[i][3] + bv[3];
            o1.x = acc[i][4] + bv[4]; o1.y = acc[i][5] + bv[5];
            o1.z = acc[i][6] + bv[6]; o1.w = acc[i][7] + bv[7];
            *reinterpret_cast<float4*>(Y + (size_t)r * M + col)     = o0;
            *reinterpret_cast<float4*>(Y + (size_t)r * M + col + 4) = o1;
        }
    }
}

// ---------------- fused dual GEMM (BN=64): for narrow layers ---------------
template <int K, int M>
__global__ __launch_bounds__(256, 3) void k_gemm_dual64(
    const float* __restrict__ X,
    const float* __restrict__ Wl, const float* __restrict__ bl,
    const float* __restrict__ Wr, const float* __restrict__ br,
    float* __restrict__ Yl, float* __restrict__ Yr, int rows)
{
    constexpr int NC = K / 16;
    __shared__ float As[3][128][20];
    __shared__ float Bs[3][16][68];

    int block_row = blockIdx.y * 128;
    int block_col = blockIdx.x * 64;
    int t = threadIdx.x;
    int tx = t & 15;
    int ty = t >> 4;

    uint32_t sA = smem_u32(&As[0][0][0]);
    uint32_t sB = smem_u32(&Bs[0][0][0]);
    constexpr uint32_t A_BUF = 128 * 20 * 4;
    constexpr uint32_t B_BUF = 16 * 68 * 4;

    int a_r[2], a_q[2];
    #pragma unroll
    for (int it = 0; it < 2; it++) {
        int slot = t + it * 256;
        a_r[it] = slot >> 2;
        a_q[it] = slot & 3;
    }
    int b_k = t >> 4;
    int b_n = (t & 15) * 4;
    int gcb = block_col + b_n;
    const float* Wp = (gcb < M) ? (Wl + gcb) : (Wr + gcb - M);

    float acc[8][4];
    #pragma unroll
    for (int i = 0; i < 8; i++)
        #pragma unroll
        for (int j = 0; j < 4; j++) acc[i][j] = 0.f;

    auto issue_copy = [&](int c, int buf) {
        int k0 = c * 16;
        #pragma unroll
        for (int it = 0; it < 2; it++) {
            int grow = block_row + a_r[it];
            uint32_t dst = sA + buf * A_BUF + (a_r[it] * 20 + a_q[it] * 4) * 4;
            cp16(dst, X + (size_t)grow * K + k0 + a_q[it] * 4, (grow < rows) ? 16 : 0);
        }
        {
            uint32_t dst = sB + buf * B_BUF + (b_k * 68 + b_n) * 4;
            cp16(dst, Wp + (size_t)(k0 + b_k) * M, 16);
        }
        CP_COMMIT();
    };

    issue_copy(0, 0);
    if (NC > 1) issue_copy(1, 1);

    #pragma unroll 1
    for (int c = 0; c < NC; c++) {
        int cb = c % 3;
        if (c + 1 < NC) { CP_WAIT1(); } else { CP_WAIT0(); }
        __syncthreads();
        if (c + 2 < NC) issue_copy(c + 2, (c + 2) % 3);

        const float* pA = &As[cb][ty * 8][0];
        const float* pB = &Bs[cb][0][tx * 4];

        float fa[2][8], fb[2][4];
        #pragma unroll
        for (int i = 0; i < 8; i++) fa[0][i] = pA[i * 20];
        *reinterpret_cast<float4*>(&fb[0][0]) = *reinterpret_cast<const float4*>(pB);

        #pragma unroll
        for (int k = 0; k < 16; k++) {
            int cur = k & 1, nxt = (k + 1) & 1;
            if (k < 15) {
                #pragma unroll
                for (int i = 0; i < 8; i++) fa[nxt][i] = pA[i * 20 + k + 1];
                *reinterpret_cast<float4*>(&fb[nxt][0]) =
                    *reinterpret_cast<const float4*>(pB + (k + 1) * 68);
            }
            #pragma unroll
            for (int i = 0; i < 8; i++)
                #pragma unroll
                for (int j = 0; j < 4; j++)
                    acc[i][j] += fa[cur][i] * fb[cur][j];
        }
    }

    int gce = block_col + tx * 4;
    float* Y = (gce < M) ? Yl : Yr;
    const float* bb = (gce < M) ? bl : br;
    int col = (gce < M) ? gce : gce - M;
    float bv[4];
    #pragma unroll
    for (int j = 0; j < 4; j++) bv[j] = bb[col + j];

    #pragma unroll
    for (int i = 0; i < 8; i++) {
        int r = block_row + ty * 8 + i;
        if (r < rows) {
            float4 o;
            o.x = acc[i][0] + bv[0]; o.y = acc[i][1] + bv[1];
            o.z = acc[i][2] + bv[2]; o.w = acc[i][3] + bv[3];
            *reinterpret_cast<float4*>(Y + (size_t)r * M + col) = o;
        }
    }
}

// ---------------- edge attention H=4: one warp per (node, head-pair) -------
// warp w handles node w>>1, half (w&1): 128 floats = 1 float4/lane.
// Lane's chunk lies in head (2*half + (lane>>4)); butterfly within 16-lane
// groups; softmax state group-local. Depth-3 rotating gather pipeline.
// Halves register pressure and doubles warp-level MLP vs full-row warps.
__global__ __launch_bounds__(256) void k_edge_attn4(
    const float* __restrict__ att,
    const float* __restrict__ bias,
    int layer)
{
    const unsigned FULL = 0xffffffffu;
    int warp = (blockIdx.x * blockDim.x + threadIdx.x) >> 5;
    int lane = threadIdx.x & 31;
    int wloc = threadIdx.x >> 5;
    int dn   = warp >> 1;
    int half = warp & 1;
    int q    = half * 32 + lane;   // float4 index within the 64-float4 row

    float sum = 0.f, sumsq = 0.f;

    if (dn < NN) {
        float4 xr = reinterpret_cast<const float4*>(&g_xr[(size_t)dn * 256])[q];
        float4 at = reinterpret_cast<const float4*>(att)[q];

        int start = g_rowptr[dn];
        int end   = g_rowptr[dn + 1];

        float m = -INFINITY, den = 0.f;
        float4 acc = make_float4(0.f, 0.f, 0.f, 0.f);

        for (int base = start; base < end; base += 32) {
            int j = base + lane;
            int myS = (j < end) ? g_eidx[j] : 0;
            int cnt = min(32, end - base);

            float4 v, w, u;
            {
                int s = __shfl_sync(FULL, myS, 0);
                v = reinterpret_cast<const float4*>(&g_xl[(size_t)s * 256])[q];
            }
            if (cnt > 1) {
                int s = __shfl_sync(FULL, myS, 1);
                w = reinterpret_cast<const float4*>(&g_xl[(size_t)s * 256])[q];
            }
            if (cnt > 2) {
                int s = __shfl_sync(FULL, myS, 2);
                u = reinterpret_cast<const float4*>(&g_xl[(size_t)s * 256])[q];
            }

            for (int i = 0; i < cnt; i++) {
                float4 e;
                if (i + 3 < cnt) {
                    int s = __shfl_sync(FULL, myS, i + 3);
                    e = reinterpret_cast<const float4*>(&g_xl[(size_t)s * 256])[q];
                }
                float p = lrelu(v.x + xr.x) * at.x + lrelu(v.y + xr.y) * at.y
                        + lrelu(v.z + xr.z) * at.z + lrelu(v.w + xr.w) * at.w;
                #pragma unroll
                for (int off = 1; off < 16; off <<= 1)
                    p += __shfl_xor_sync(FULL, p, off);
                if (p > m) {
                    float sc = __expf(m - p);
                    den *= sc;
                    acc.x *= sc; acc.y *= sc; acc.z *= sc; acc.w *= sc;
                    m = p;
                }
                float wg = __expf(p - m);
                den += wg;
                acc.x += wg * v.x; acc.y += wg * v.y;
                acc.z += wg * v.z; acc.w += wg * v.w;
                v = w; w = u; u = e;
            }
        }

        float inv = (den > 0.f) ? (1.f / den) : 0.f;
        float4 bi = reinterpret_cast<const float4*>(bias)[q];
        float4 o;
        o.x = acc.x * inv + bi.x; o.y = acc.y * inv + bi.y;
        o.z = acc.z * inv + bi.z; o.w = acc.w * inv + bi.w;
        reinterpret_cast<float4*>(&g_acc[(size_t)dn * 256])[q] = o;
        sum   += o.x + o.y + o.z + o.w;
        sumsq += o.x * o.x + o.y * o.y + o.z * o.z + o.w * o.w;
    }

    #pragma unroll
    for (int off = 16; off > 0; off >>= 1) {
        sum   += __shfl_xor_sync(FULL, sum,   off);
        sumsq += __shfl_xor_sync(FULL, sumsq, off);
    }
    __shared__ float sr[8], sr2[8];
    if (lane == 0) { sr[wloc] = sum; sr2[wloc] = sumsq; }
    __syncthreads();
    if (threadIdx.x == 0) {
        float a = 0.f, b = 0.f;
        #pragma unroll
        for (int i = 0; i < 8; i++) { a += sr[i]; b += sr2[i]; }
        atomicAdd(&g_red[2 * layer],     a);
        atomicAdd(&g_red[2 * layer + 1], b);
    }
}

// ---------------- edge attention H=1: 16-lane groups, 2 nodes/warp ---------
__global__ __launch_bounds__(256) void k_edge_attn1(
    const float* __restrict__ att,
    const float* __restrict__ bias,
    int layer)
{
    const unsigned FULL = 0xffffffffu;
    int tid  = blockIdx.x * blockDim.x + threadIdx.x;
    int dn   = tid >> 4;
    int gl   = threadIdx.x & 15;
    int lane = threadIdx.x & 31;
    int half = lane & 16;
    const unsigned GMASK = 0xFFFFu << half;
    int wloc = threadIdx.x >> 5;

    float sum = 0.f, sumsq = 0.f;

    if (dn < NN) {
        float4 xr = reinterpret_cast<const float4*>(&g_xr[(size_t)dn * 64])[gl];
        float4 at = reinterpret_cast<const float4*>(att)[gl];

        int start = g_rowptr[dn];
        int end   = g_rowptr[dn + 1];

        float m = -INFINITY, den = 0.f;
        float4 acc = make_float4(0.f, 0.f, 0.f, 0.f);

        for (int base = start; base < end; base += 16) {
            int j = base + gl;
            int myS = (j < end) ? g_eidx[j] : 0;
            int cnt = min(16, end - base);

            float4 v, w, u;
            {
                int s = __shfl_sync(GMASK, myS, half | 0);
                v = reinterpret_cast<const float4*>(&g_xl[(size_t)s * 64])[gl];
            }
            if (cnt > 1) {
                int s = __shfl_sync(GMASK, myS, half | 1);
                w = reinterpret_cast<const float4*>(&g_xl[(size_t)s * 64])[gl];
            }
            if (cnt > 2) {
                int s = __shfl_sync(GMASK, myS, half | 2);
                u = reinterpret_cast<const float4*>(&g_xl[(size_t)s * 64])[gl];
            }

            for (int i = 0; i < cnt; i++) {
                float4 e;
                if (i + 3 < cnt) {
                    int s = __shfl_sync(GMASK, myS, half | (i + 3));
                    e = reinterpret_cast<const float4*>(&g_xl[(size_t)s * 64])[gl];
                }
                float p = lrelu(v.x + xr.x) * at.x + lrelu(v.y + xr.y) * at.y
                        + lrelu(v.z + xr.z) * at.z + lrelu(v.w + xr.w) * at.w;
                #pragma unroll
                for (int off = 1; off < 16; off <<= 1)
                    p += __shfl_xor_sync(GMASK, p, off);
                if (p > m) {
                    float sc = __expf(m - p);
                    den *= sc;
                    acc.x *= sc; acc.y *= sc; acc.z *= sc; acc.w *= sc;
                    m = p;
                }
                float wg = __expf(p - m);
                den += wg;
                acc.x += wg * v.x; acc.y += wg * v.y;
                acc.z += wg * v.z; acc.w += wg * v.w;
                v = w; w = u; u = e;
            }
        }

        float inv = (den > 0.f) ? (1.f / den) : 0.f;
        float4 bi = reinterpret_cast<const float4*>(bias)[gl];
        float4 o;
        o.x = acc.x * inv + bi.x; o.y = acc.y * inv + bi.y;
        o.z = acc.z * inv + bi.z; o.w = acc.w * inv + bi.w;
        reinterpret_cast<float4*>(&g_acc[(size_t)dn * 64])[gl] = o;
        sum   += o.x + o.y + o.z + o.w;
        sumsq += o.x * o.x + o.y * o.y + o.z * o.z + o.w * o.w;
    }

    #pragma unroll
    for (int off = 16; off > 0; off >>= 1) {
        sum   += __shfl_xor_sync(FULL, sum,   off);
        sumsq += __shfl_xor_sync(FULL, sumsq, off);
    }
    __shared__ float sr[8], sr2[8];
    if (lane == 0) { sr[wloc] = sum; sr2[wloc] = sumsq; }
    __syncthreads();
    if (threadIdx.x == 0) {
        float a = 0.f, b = 0.f;
        #pragma unroll
        for (int i = 0; i < 8; i++) { a += sr[i]; b += sr2[i]; }
        atomicAdd(&g_red[2 * layer],     a);
        atomicAdd(&g_red[2 * layer + 1], b);
    }
}

// ---------------- LN apply (float4; +relu, +residual, +optional pool) ------
__global__ __launch_bounds__(256) void k_ln_apply(
    const float* __restrict__ gamma, const float* __restrict__ beta,
    const int* __restrict__ batch,
    int count4, int DM, float invCount, int residual, int layer, int do_pool)
{
    int i = blockIdx.x * blockDim.x + threadIdx.x;
    if (i >= count4) return;
    int base = i * 4;
    int c = base % DM;
    float mu  = g_red[2 * layer] * invCount;
    float var = g_red[2 * layer + 1] * invCount - mu * mu;
    float rs  = rsqrtf(var + LN_EPS);

    float4 a = *reinterpret_cast<const float4*>(&g_acc[base]);
    float4 gm = *reinterpret_cast<const float4*>(gamma + c);
    float4 bt = *reinterpret_cast<const float4*>(beta + c);
    float4 v;
    v.x = fmaxf((a.x - mu) * rs * gm.x + bt.x, 0.f);
    v.y = fmaxf((a.y - mu) * rs * gm.y + bt.y, 0.f);
    v.z = fmaxf((a.z - mu) * rs * gm.z + bt.z, 0.f);
    v.w = fmaxf((a.w - mu) * rs * gm.w + bt.w, 0.f);
    if (residual) {
        float4 h = *reinterpret_cast<const float4*>(&g_h[base]);
        v.x += h.x; v.y += h.y; v.z += h.z; v.w += h.w;
    }
    *reinterpret_cast<float4*>(&g_h[base]) = v;
    if (do_pool) {
        int node = base >> 6;
        int g = batch[node];
        atomicAdd(&g_pool[g * 64 + c],     v.x);
        atomicAdd(&g_pool[g * 64 + c + 1], v.y);
        atomicAdd(&g_pool[g * 64 + c + 2], v.z);
        atomicAdd(&g_pool[g * 64 + c + 3], v.w);
    }
}

// ---------------- MLP head ----------------
__global__ __launch_bounds__(64) void k_mlp(
    const float* __restrict__ Wh1, const float* __restrict__ bh1,
    const float* __restrict__ Wh2, const float* __restrict__ bh2,
    float* __restrict__ out)
{
    int g = blockIdx.x;
    int j = threadIdx.x;
    __shared__ float z[64];
    __shared__ float red[64];
    float cnt = fmaxf(g_pcnt[g], 1.f);
    z[j] = g_pool[g * 64 + j] / cnt;
    __syncthreads();
    float hv = bh1[j];
    #pragma unroll 8
    for (int k = 0; k < 64; k++) hv += z[k] * Wh1[k * 64 + j];
    hv = fmaxf(hv, 0.f);
    red[j] = hv * Wh2[j];
    __syncthreads();
    for (int off = 32; off > 0; off >>= 1) {
        if (j < off) red[j] += red[j + off];
        __syncthreads();
    }
    if (j == 0) out[g] = red[0] + bh2[0];
}

// ---------------- host orchestration ----------------
extern "C" void kernel_launch(void* const* d_in, const int* in_sizes, int n_in,
                              void* d_out, int out_size)
{
    const float* x     = (const float*)d_in[0];
    const int*   ei    = (const int*)d_in[1];
    const int*   srcA  = ei;
    const int*   dstA  = ei + EE;
    const int*   batch = (const int*)d_in[2];

    const float* Wl[3];  const float* bl[3];
    const float* Wr[3];  const float* br[3];
    const float* att[3]; const float* bias[3];
    const float* lng[3]; const float* lnb[3];
    for (int l = 0; l < 3; l++) {
        int base = 3 + 8 * l;
        Wl[l]   = (const float*)d_in[base + 0];
        bl[l]   = (const float*)d_in[base + 1];
        Wr[l]   = (const float*)d_in[base + 2];
        br[l]   = (const float*)d_in[base + 3];
        att[l]  = (const float*)d_in[base + 4];
        bias[l] = (const float*)d_in[base + 5];
        lng[l]  = (const float*)d_in[base + 6];
        lnb[l]  = (const float*)d_in[base + 7];
    }
    const float* Wh1 = (const float*)d_in[27];
    const float* bh1 = (const float*)d_in[28];
    const float* Wh2 = (const float*)d_in[29];
    const float* bh2 = (const float*)d_in[30];
    float* out = (float*)d_out;

    float *p_xl, *p_xr, *p_h;
    cudaGetSymbolAddress((void**)&p_xl, g_xl);
    cudaGetSymbolAddress((void**)&p_xr, g_xr);
    cudaGetSymbolAddress((void**)&p_h,  g_h);

    const int dm_[3]  = {256, 64, 64};
    const int res_[3] = {0, 0, 1};
    const int RT = (NN + 127) / 128;

    // ---- fork: CSR/init chain on side stream, gemm l0 on main stream ----
    cudaEventRecord(g_ev0, 0);
    cudaStreamWaitEvent(g_s1, g_ev0, 0);

    k_gemm_dual<128, 256><<<dim3(4, RT), 256>>>(x, Wl[0], bl[0], Wr[0], br[0], p_xl, p_xr, NN);

    k_zero_misc<<<(NN + 255) / 256, 256, 0, g_s1>>>();
    k_hist_pcnt<<<(EE + 255) / 256, 256, 0, g_s1>>>(dstA, batch);
    k_scan1<<<NCHUNKS, 1024, 0, g_s1>>>();
    k_scan2<<<1, 64, 0, g_s1>>>();
    k_scan3<<<(NN + 255) / 256, 256, 0, g_s1>>>();
    k_scatter<<<(EE + 255) / 256, 256, 0, g_s1>>>(srcA, dstA);
    cudaEventRecord(g_ev1, g_s1);

    cudaStreamWaitEvent(0, g_ev1, 0);

    for (int l = 0; l < 3; l++) {
        if (l == 1)
            k_gemm_dual64<256, 64><<<dim3(2, RT), 256>>>(p_h, Wl[1], bl[1], Wr[1], br[1], p_xl, p_xr, NN);
        else if (l == 2)
            k_gemm_dual64<64, 64><<<dim3(2, RT), 256>>>(p_h, Wl[2], bl[2], Wr[2], br[2], p_xl, p_xr, NN);

        if (l == 0) {
            int blocks = (NN * 2 * 32 + 255) / 256;   // 2 warps per node
            k_edge_attn4<<<blocks, 256>>>(att[l], bias[l], l);
        } else {
            int blocks = (NN * 16 + 255) / 256;
            k_edge_attn1<<<blocks, 256>>>(att[l], bias[l], l);
        }

        int count4 = NN * dm_[l] / 4;
        k_ln_apply<<<(count4 + 255) / 256, 256>>>(lng[l], lnb[l], batch, count4, dm_[l],
                                                  1.f / (float)(NN * dm_[l]),
                                                  res_[l], l, l == 2);
    }

    k_mlp<<<GG, 64>>>(Wh1, bh1, Wh2, bh2, out);

    (void)in_sizes; (void)n_in; (void)out_size;
}